// round 1
// baseline (speedup 1.0000x reference)
#include <cuda_runtime.h>
#include <cuda_bf16.h>
#include <cstdint>

// Problem constants
#define B_  4
#define N_  4096
#define M1_ 2048
#define M2_ 512
#define F1_ 64     // SA1 output features
#define F2_ 128    // SA2 output features
#define F3_ 1024   // final features
#define LF_ 64
#define MAXNBR 128

// ---------------- device scratch (no allocation allowed) ----------------
__device__ float g_p1  [B_ * N_  * F1_];   // per-point part of SA1 message
__device__ float g_h1  [B_ * M1_ * F1_];   // SA1 output
__device__ float g_ctr1[B_ * M1_ * 2];     // SA1 centers
__device__ float g_p2  [B_ * M1_ * F2_];   // per-point part of SA2 message
__device__ float g_h2  [B_ * M2_ * F2_];   // SA2 output
__device__ float g_ctr2[B_ * M2_ * 2];     // SA2 centers
__device__ float g_pmax[B_ * 8 * F3_];     // partial maxes for final pool

// ---------------- kernel 1: lf = tanh(tanh(x W1 + b1) W2 + b2) ----------
// 64 threads/block, 32 rows/block. grid = (B*N)/32 = 512
__global__ void lf_kernel(const float* __restrict__ x,
                          const float* __restrict__ W1, const float* __restrict__ b1,
                          const float* __restrict__ W2, const float* __restrict__ b2,
                          float* __restrict__ lf_out) {
    __shared__ float sW2[64 * 64];
    __shared__ float sW1[2 * 64];
    __shared__ float sb1[64], sb2[64];
    __shared__ float st1[64];
    int tid = threadIdx.x;
    for (int i = tid; i < 64 * 64; i += 64) sW2[i] = W2[i];
    sW1[tid] = W1[tid]; sW1[64 + tid] = W1[64 + tid];
    sb1[tid] = b1[tid]; sb2[tid] = b2[tid];
    __syncthreads();
    int row0 = blockIdx.x * 32;
    for (int r = 0; r < 32; r++) {
        int row = row0 + r;
        float x0 = x[row * 2], x1 = x[row * 2 + 1];
        float t1 = tanhf(x0 * sW1[tid] + x1 * sW1[64 + tid] + sb1[tid]);
        st1[tid] = t1;
        __syncthreads();
        float acc = sb2[tid];
#pragma unroll
        for (int c = 0; c < 64; c++) acc = fmaf(st1[c], sW2[c * 64 + tid], acc);
        lf_out[row * 64 + tid] = tanhf(acc);
        __syncthreads();
    }
}

// ---------------- kernel 2: p1[j] = [lf_j, zone_j] @ c1W[:65] + c1b ------
__global__ void p1_kernel(const float* __restrict__ lf, const float* __restrict__ zones,
                          const float* __restrict__ c1W, const float* __restrict__ c1b) {
    __shared__ float sW[65 * 64];
    __shared__ float sb[64];
    __shared__ float srow[64];
    int tid = threadIdx.x;  // 64
    for (int i = tid; i < 65 * 64; i += 64) sW[i] = c1W[i];
    sb[tid] = c1b[tid];
    __syncthreads();
    int row0 = blockIdx.x * 32;
    for (int r = 0; r < 32; r++) {
        int row = row0 + r;
        srow[tid] = lf[row * 64 + tid];
        __syncthreads();
        float z = zones[row];
        float acc = fmaf(z, sW[64 * 64 + tid], sb[tid]);
#pragma unroll
        for (int c = 0; c < 64; c++) acc = fmaf(srow[c], sW[c * 64 + tid], acc);
        g_p1[row * 64 + tid] = acc;
        __syncthreads();
    }
}

// ---------------- kernel 3/5: farthest point sampling --------------------
// one block per batch, 1024 threads, P points per thread (register resident).
// LEVEL 0: pos = x input, ctr -> g_ctr1. LEVEL 1: pos = g_ctr1, ctr -> g_ctr2.
template <int P, int N, int M, int LEVEL>
__global__ void fps_kernel(const float* __restrict__ pos_in) {
    const int T = 1024;
    int b = blockIdx.x;
    int tid = threadIdx.x;
    const float2* p = (LEVEL == 0) ? (const float2*)(pos_in + (size_t)b * N * 2)
                                   : (const float2*)(g_ctr1 + (size_t)b * N * 2);
    float* cout = (LEVEL == 0) ? (g_ctr1 + (size_t)b * M * 2)
                               : (g_ctr2 + (size_t)b * M * 2);

    __shared__ float2 spos[N_];   // max 4096 -> 32KB
    __shared__ unsigned swv[32];
    __shared__ unsigned swi[32];
    __shared__ int s_last;

    float px[P], py[P], md[P];
#pragma unroll
    for (int k = 0; k < P; k++) {
        int j = tid + k * T;
        float2 v = p[j];
        spos[j] = v;
        px[k] = v.x; py[k] = v.y;
        md[k] = 1e10f;
    }
    if (tid == 0) {
        float2 c0 = p[0];
        cout[0] = c0.x; cout[1] = c0.y;
        s_last = 0;
    }
    __syncthreads();

    int last = 0;
    int wid = tid >> 5, lane = tid & 31;
    for (int t = 1; t < M; t++) {
        float lx = spos[last].x, ly = spos[last].y;
        unsigned bv = 0u;
        unsigned bi = 0xFFFFFFFFu;
#pragma unroll
        for (int k = 0; k < P; k++) {
            float dx = px[k] - lx, dy = py[k] - ly;
            float d2 = dx * dx + dy * dy;
            md[k] = fminf(md[k], d2);
            unsigned vb = __float_as_uint(md[k]);  // md >= 0: uint order == float order
            unsigned idx = (unsigned)(tid + k * T);
            if (vb > bv || (vb == bv && idx < bi)) { bv = vb; bi = idx; }
        }
        // warp argmax with first-occurrence (min index) tie-break
        unsigned wmax = __reduce_max_sync(0xFFFFFFFFu, bv);
        unsigned cand = (bv == wmax) ? bi : 0xFFFFFFFFu;
        unsigned wbi  = __reduce_min_sync(0xFFFFFFFFu, cand);
        if (lane == 0) { swv[wid] = wmax; swi[wid] = wbi; }
        __syncthreads();
        if (wid == 0) {
            unsigned v2 = swv[lane];
            unsigned i2 = swi[lane];
            unsigned m2 = __reduce_max_sync(0xFFFFFFFFu, v2);
            unsigned c2 = (v2 == m2) ? i2 : 0xFFFFFFFFu;
            unsigned gi = __reduce_min_sync(0xFFFFFFFFu, c2);
            if (lane == 0) {
                s_last = (int)gi;
                float2 w = spos[gi];
                cout[t * 2] = w.x; cout[t * 2 + 1] = w.y;
            }
        }
        __syncthreads();
        last = s_last;
    }
}

// ---------------- kernel 4: SA1 (radius scan + max-aggregate) ------------
// one block per (center, batch), 64 threads (= F1 features)
__global__ void sa1_kernel(const float* __restrict__ x, const float* __restrict__ c1W) {
    const int N = N_, M = M1_, F = F1_;
    int i = blockIdx.x, b = blockIdx.y, tid = threadIdx.x;
    __shared__ float sdx[MAXNBR], sdy[MAXNBR];
    __shared__ int   snb[MAXNBR];
    __shared__ int   scnt;
    if (tid == 0) scnt = 0;
    __syncthreads();
    float cx = g_ctr1[(b * M + i) * 2], cy = g_ctr1[(b * M + i) * 2 + 1];
    const float2* pos = (const float2*)(x + (size_t)b * N * 2);
    for (int j = tid; j < N; j += F) {
        float2 pj = pos[j];
        float dx = pj.x - cx, dy = pj.y - cy;
        float d2 = dx * dx + dy * dy;
        if (d2 <= 0.25f) {
            int s = atomicAdd(&scnt, 1);
            if (s < MAXNBR) { snb[s] = j; sdx[s] = dx; sdy[s] = dy; }
        }
    }
    __syncthreads();
    int cnt = min(scnt, MAXNBR);
    float wx = c1W[65 * 64 + tid];
    float wy = c1W[66 * 64 + tid];
    float mx = -1e9f;
    const float* pb = g_p1 + (size_t)b * N * F;
    for (int n = 0; n < cnt; n++) {
        float m = fmaf(sdx[n], wx, fmaf(sdy[n], wy, pb[snb[n] * F + tid]));
        mx = fmaxf(mx, m);
    }
    g_h1[((size_t)b * M + i) * F + tid] = mx;
}

// ---------------- kernel 6: p2[j] = h1_j @ c2W[:64] + c2b ----------------
__global__ void p2_kernel(const float* __restrict__ c2W, const float* __restrict__ c2b) {
    __shared__ float sW[64 * 128];
    __shared__ float sb[128];
    __shared__ float srow[64];
    int tid = threadIdx.x;  // 128
    for (int i = tid; i < 64 * 128; i += 128) sW[i] = c2W[i];
    sb[tid] = c2b[tid];
    __syncthreads();
    int row0 = blockIdx.x * 32;
    for (int r = 0; r < 32; r++) {
        int row = row0 + r;
        if (tid < 64) srow[tid] = g_h1[row * 64 + tid];
        __syncthreads();
        float acc = sb[tid];
#pragma unroll
        for (int c = 0; c < 64; c++) acc = fmaf(srow[c], sW[c * 128 + tid], acc);
        g_p2[row * 128 + tid] = acc;
        __syncthreads();
    }
}

// ---------------- kernel 7: SA2 ------------------------------------------
__global__ void sa2_kernel(const float* __restrict__ c2W) {
    const int N = M1_, M = M2_, F = F2_;
    int i = blockIdx.x, b = blockIdx.y, tid = threadIdx.x;
    __shared__ float sdx[MAXNBR], sdy[MAXNBR];
    __shared__ int   snb[MAXNBR];
    __shared__ int   scnt;
    if (tid == 0) scnt = 0;
    __syncthreads();
    float cx = g_ctr2[(b * M + i) * 2], cy = g_ctr2[(b * M + i) * 2 + 1];
    const float2* pos = (const float2*)(g_ctr1 + (size_t)b * N * 2);
    for (int j = tid; j < N; j += F) {
        float2 pj = pos[j];
        float dx = pj.x - cx, dy = pj.y - cy;
        float d2 = dx * dx + dy * dy;
        if (d2 <= 1.0f) {
            int s = atomicAdd(&scnt, 1);
            if (s < MAXNBR) { snb[s] = j; sdx[s] = dx; sdy[s] = dy; }
        }
    }
    __syncthreads();
    int cnt = min(scnt, MAXNBR);
    float wx = c2W[64 * 128 + tid];
    float wy = c2W[65 * 128 + tid];
    float mx = -1e9f;
    const float* pb = g_p2 + (size_t)b * N * F;
    for (int n = 0; n < cnt; n++) {
        float m = fmaf(sdx[n], wx, fmaf(sdy[n], wy, pb[snb[n] * F + tid]));
        mx = fmaxf(mx, m);
    }
    g_h2[((size_t)b * M + i) * F + tid] = mx;
}

// ---------------- kernel 8: g = [h2, ctr2] @ c3W + c3b, partial max ------
// grid (8 fchunks, 8 rowchunks, B), 128 threads; 64 accumulators/thread
__global__ void final_partial(const float* __restrict__ W, const float* __restrict__ bias) {
    int fchunk = blockIdx.x, rchunk = blockIdx.y, b = blockIdx.z;
    int tid = threadIdx.x;  // 128
    int f = fchunk * 128 + tid;
    __shared__ float sh[64][132];
    int r0 = rchunk * 64;
    for (int e = tid; e < 64 * 130; e += 128) {
        int r = e / 130, c = e % 130;
        float v;
        if (c < 128) v = g_h2[((size_t)b * M2_ + r0 + r) * 128 + c];
        else         v = g_ctr2[(b * M2_ + r0 + r) * 2 + (c - 128)];
        sh[r][c] = v;
    }
    __syncthreads();
    float acc[64];
#pragma unroll
    for (int r = 0; r < 64; r++) acc[r] = 0.0f;
    for (int c = 0; c < 130; c++) {
        float w = W[c * 1024 + f];
#pragma unroll
        for (int r = 0; r < 64; r++) acc[r] = fmaf(sh[r][c], w, acc[r]);
    }
    float mx = acc[0];
#pragma unroll
    for (int r = 1; r < 64; r++) mx = fmaxf(mx, acc[r]);
    g_pmax[(b * 8 + rchunk) * 1024 + f] = mx + bias[f];
}

// ---------------- kernel 9: reduce 8 partial maxes -> gf -----------------
__global__ void final_reduce(float* __restrict__ gf) {
    int b = blockIdx.x, f = threadIdx.x;  // 1024 threads
    float mx = g_pmax[(b * 8) * 1024 + f];
#pragma unroll
    for (int r = 1; r < 8; r++) mx = fmaxf(mx, g_pmax[(b * 8 + r) * 1024 + f]);
    gf[b * 1024 + f] = mx;
}

// ---------------- launch ---------------------------------------------------
extern "C" void kernel_launch(void* const* d_in, const int* in_sizes, int n_in,
                              void* d_out, int out_size) {
    const float* x     = (const float*)d_in[0];
    const float* zones = (const float*)d_in[1];
    const float* lf_W1 = (const float*)d_in[2];
    const float* lf_b1 = (const float*)d_in[3];
    const float* lf_W2 = (const float*)d_in[4];
    const float* lf_b2 = (const float*)d_in[5];
    const float* c1_W  = (const float*)d_in[6];
    const float* c1_b  = (const float*)d_in[7];
    const float* c2_W  = (const float*)d_in[8];
    const float* c2_b  = (const float*)d_in[9];
    const float* c3_W  = (const float*)d_in[10];
    const float* c3_b  = (const float*)d_in[11];

    float* lf_out = (float*)d_out;                         // [B,N,64]
    float* gf_out = (float*)d_out + (size_t)B_ * N_ * LF_; // [B,1024]

    // 1) local features
    lf_kernel<<<(B_ * N_) / 32, 64>>>(x, lf_W1, lf_b1, lf_W2, lf_b2, lf_out);
    // 2) per-point message part for SA1
    p1_kernel<<<(B_ * N_) / 32, 64>>>(lf_out, zones, c1_W, c1_b);
    // 3) FPS level 1
    fps_kernel<4, N_, M1_, 0><<<B_, 1024>>>(x);
    // 4) SA1
    sa1_kernel<<<dim3(M1_, B_), F1_>>>(x, c1_W);
    // 5) FPS level 2
    fps_kernel<2, M1_, M2_, 1><<<B_, 1024>>>(nullptr);
    // 6) per-point message part for SA2
    p2_kernel<<<(B_ * M1_) / 32, 128>>>(c2_W, c2_b);
    // 7) SA2
    sa2_kernel<<<dim3(M2_, B_), F2_>>>(c2_W);
    // 8) final projection + partial max pool
    final_partial<<<dim3(8, 8, B_), 128>>>(c3_W, c3_b);
    // 9) reduce to gf
    final_reduce<<<B_, 1024>>>(gf_out);
}

// round 2
// speedup vs baseline: 1.0262x; 1.0262x over previous
#include <cuda_runtime.h>
#include <cuda_bf16.h>
#include <cstdint>

// Problem constants
#define B_  4
#define N_  4096
#define M1_ 2048
#define M2_ 512
#define F1_ 64
#define F2_ 128
#define F3_ 1024
#define LF_ 64
#define MAXNBR 128

// ---------------- device scratch ----------------
__device__ float g_p1  [B_ * N_  * F1_];
__device__ float g_h1  [B_ * M1_ * F1_];
__device__ float g_ctr1[B_ * M1_ * 2];
__device__ float g_p2  [B_ * M1_ * F2_];
__device__ float g_h2  [B_ * M2_ * F2_];
__device__ float g_ctr2[B_ * M2_ * 2];
__device__ float g_pmax[B_ * 8 * F3_];

// ---------------- kernel 1: lf = tanh(tanh(x W1 + b1) W2 + b2) ----------
__global__ void lf_kernel(const float* __restrict__ x,
                          const float* __restrict__ W1, const float* __restrict__ b1,
                          const float* __restrict__ W2, const float* __restrict__ b2,
                          float* __restrict__ lf_out) {
    __shared__ float sW2[64 * 64];
    __shared__ float sW1[2 * 64];
    __shared__ float sb1[64], sb2[64];
    __shared__ float st1[64];
    int tid = threadIdx.x;
    for (int i = tid; i < 64 * 64; i += 64) sW2[i] = W2[i];
    sW1[tid] = W1[tid]; sW1[64 + tid] = W1[64 + tid];
    sb1[tid] = b1[tid]; sb2[tid] = b2[tid];
    __syncthreads();
    int row0 = blockIdx.x * 32;
    for (int r = 0; r < 32; r++) {
        int row = row0 + r;
        float x0 = x[row * 2], x1 = x[row * 2 + 1];
        float t1 = tanhf(x0 * sW1[tid] + x1 * sW1[64 + tid] + sb1[tid]);
        st1[tid] = t1;
        __syncthreads();
        float acc = sb2[tid];
#pragma unroll
        for (int c = 0; c < 64; c++) acc = fmaf(st1[c], sW2[c * 64 + tid], acc);
        lf_out[row * 64 + tid] = tanhf(acc);
        __syncthreads();
    }
}

// ---------------- kernel 2: p1[j] = [lf_j, zone_j] @ c1W[:65] + c1b ------
__global__ void p1_kernel(const float* __restrict__ lf, const float* __restrict__ zones,
                          const float* __restrict__ c1W, const float* __restrict__ c1b) {
    __shared__ float sW[65 * 64];
    __shared__ float sb[64];
    __shared__ float srow[64];
    int tid = threadIdx.x;  // 64
    for (int i = tid; i < 65 * 64; i += 64) sW[i] = c1W[i];
    sb[tid] = c1b[tid];
    __syncthreads();
    int row0 = blockIdx.x * 32;
    for (int r = 0; r < 32; r++) {
        int row = row0 + r;
        srow[tid] = lf[row * 64 + tid];
        __syncthreads();
        float z = zones[row];
        float acc = fmaf(z, sW[64 * 64 + tid], sb[tid]);
#pragma unroll
        for (int c = 0; c < 64; c++) acc = fmaf(srow[c], sW[c * 64 + tid], acc);
        g_p1[row * 64 + tid] = acc;
        __syncthreads();
    }
}

// ---------------- FPS: 512 threads, P points/thread, 1 barrier/iter ------
// Exact first-occurrence argmax tie-break at all levels.
template <int P, int N, int M, int LEVEL>
__global__ void fps_kernel(const float* __restrict__ pos_in) {
    const int T = 512;          // threads
    const int NW = T / 32;      // 16 warps
    int b = blockIdx.x;
    int tid = threadIdx.x;
    const float2* p = (LEVEL == 0) ? (const float2*)(pos_in + (size_t)b * N * 2)
                                   : (const float2*)(g_ctr1 + (size_t)b * N * 2);
    float* cout = (LEVEL == 0) ? (g_ctr1 + (size_t)b * M * 2)
                               : (g_ctr2 + (size_t)b * M * 2);

    __shared__ float2 spos[N];
    __shared__ unsigned swv[2][NW];
    __shared__ unsigned swi[2][NW];

    float px[P], py[P], md[P];
#pragma unroll
    for (int k = 0; k < P; k++) {
        int j = tid + k * T;
        float2 v = p[j];
        spos[j] = v;
        px[k] = v.x; py[k] = v.y;
        md[k] = 1e10f;
    }
    if (tid == 0) {
        float2 c0 = p[0];
        cout[0] = c0.x; cout[1] = c0.y;
    }
    __syncthreads();

    int gi = 0;
    int wid = tid >> 5, lane = tid & 31;
    for (int t = 1; t < M; t++) {
        float lx = spos[gi].x, ly = spos[gi].y;
        // update min-distances; track thread max only
        float tb = -1.0f;
#pragma unroll
        for (int k = 0; k < P; k++) {
            float dx = px[k] - lx, dy = py[k] - ly;
            float d2 = fmaf(dx, dx, dy * dy);
            md[k] = fminf(md[k], d2);
            tb = fmaxf(tb, md[k]);
        }
        // candidate index: smallest k with md==tb (idx = tid + k*T, ascending in k)
        unsigned ki = P - 1;
#pragma unroll
        for (int k = P - 2; k >= 0; k--) if (md[k] == tb) ki = (unsigned)k;
        unsigned myidx = (unsigned)tid + ki * T;
        unsigned vb = __float_as_uint(tb);   // tb >= 0: uint order == float order
        // warp argmax with min-index tie-break
        unsigned wmax = __reduce_max_sync(0xFFFFFFFFu, vb);
        unsigned cand = (vb == wmax) ? myidx : 0xFFFFFFFFu;
        unsigned wbi  = __reduce_min_sync(0xFFFFFFFFu, cand);
        // cross-warp: double-buffered smem, ONE barrier, redundant reduce in all warps
        int buf = t & 1;
        if (lane == 0) { swv[buf][wid] = wmax; swi[buf][wid] = wbi; }
        __syncthreads();
        unsigned v2 = (lane < NW) ? swv[buf][lane] : 0u;
        unsigned i2 = (lane < NW) ? swi[buf][lane] : 0xFFFFFFFFu;
        unsigned m2 = __reduce_max_sync(0xFFFFFFFFu, v2);
        unsigned c2 = (v2 == m2) ? i2 : 0xFFFFFFFFu;
        gi = (int)__reduce_min_sync(0xFFFFFFFFu, c2);
        if (tid == 0) {
            float2 w = spos[gi];
            cout[t * 2] = w.x; cout[t * 2 + 1] = w.y;
        }
    }
}

// ---------------- SA1: 128-thread radius scan, 64-thread aggregate -------
__global__ void sa1_kernel(const float* __restrict__ x, const float* __restrict__ c1W) {
    const int N = N_, M = M1_, F = F1_;
    int i = blockIdx.x, b = blockIdx.y, tid = threadIdx.x;  // 128 threads
    __shared__ float sdx[MAXNBR], sdy[MAXNBR];
    __shared__ int   snb[MAXNBR];
    __shared__ int   scnt;
    if (tid == 0) scnt = 0;
    __syncthreads();
    float cx = g_ctr1[(b * M + i) * 2], cy = g_ctr1[(b * M + i) * 2 + 1];
    const float2* pos = (const float2*)(x + (size_t)b * N * 2);
    for (int j = tid; j < N; j += 128) {
        float2 pj = pos[j];
        float dx = pj.x - cx, dy = pj.y - cy;
        float d2 = fmaf(dx, dx, dy * dy);
        if (d2 <= 0.25f) {
            int s = atomicAdd(&scnt, 1);
            if (s < MAXNBR) { snb[s] = j; sdx[s] = dx; sdy[s] = dy; }
        }
    }
    __syncthreads();
    if (tid >= F) return;
    int cnt = min(scnt, MAXNBR);
    float wx = c1W[65 * 64 + tid];
    float wy = c1W[66 * 64 + tid];
    float mx = -1e9f;
    const float* pb = g_p1 + (size_t)b * N * F;
    int n = 0;
    for (; n + 4 <= cnt; n += 4) {
        float v0 = pb[snb[n] * F + tid];
        float v1 = pb[snb[n + 1] * F + tid];
        float v2 = pb[snb[n + 2] * F + tid];
        float v3 = pb[snb[n + 3] * F + tid];
        float m0 = fmaf(sdx[n], wx, fmaf(sdy[n], wy, v0));
        float m1 = fmaf(sdx[n + 1], wx, fmaf(sdy[n + 1], wy, v1));
        float m2 = fmaf(sdx[n + 2], wx, fmaf(sdy[n + 2], wy, v2));
        float m3 = fmaf(sdx[n + 3], wx, fmaf(sdy[n + 3], wy, v3));
        mx = fmaxf(mx, fmaxf(fmaxf(m0, m1), fmaxf(m2, m3)));
    }
    for (; n < cnt; n++) {
        float m = fmaf(sdx[n], wx, fmaf(sdy[n], wy, pb[snb[n] * F + tid]));
        mx = fmaxf(mx, m);
    }
    g_h1[((size_t)b * M + i) * F + tid] = mx;
}

// ---------------- p2[j] = h1_j @ c2W[:64] + c2b ---------------------------
__global__ void p2_kernel(const float* __restrict__ c2W, const float* __restrict__ c2b) {
    __shared__ float sW[64 * 128];
    __shared__ float sb[128];
    __shared__ float srow[64];
    int tid = threadIdx.x;  // 128
    for (int i = tid; i < 64 * 128; i += 128) sW[i] = c2W[i];
    sb[tid] = c2b[tid];
    __syncthreads();
    int row0 = blockIdx.x * 32;
    for (int r = 0; r < 32; r++) {
        int row = row0 + r;
        if (tid < 64) srow[tid] = g_h1[row * 64 + tid];
        __syncthreads();
        float acc = sb[tid];
#pragma unroll
        for (int c = 0; c < 64; c++) acc = fmaf(srow[c], sW[c * 128 + tid], acc);
        g_p2[row * 128 + tid] = acc;
        __syncthreads();
    }
}

// ---------------- SA2 -----------------------------------------------------
__global__ void sa2_kernel(const float* __restrict__ c2W) {
    const int N = M1_, M = M2_, F = F2_;
    int i = blockIdx.x, b = blockIdx.y, tid = threadIdx.x;  // 128
    __shared__ float sdx[MAXNBR], sdy[MAXNBR];
    __shared__ int   snb[MAXNBR];
    __shared__ int   scnt;
    if (tid == 0) scnt = 0;
    __syncthreads();
    float cx = g_ctr2[(b * M + i) * 2], cy = g_ctr2[(b * M + i) * 2 + 1];
    const float2* pos = (const float2*)(g_ctr1 + (size_t)b * N * 2);
    for (int j = tid; j < N; j += F) {
        float2 pj = pos[j];
        float dx = pj.x - cx, dy = pj.y - cy;
        float d2 = fmaf(dx, dx, dy * dy);
        if (d2 <= 1.0f) {
            int s = atomicAdd(&scnt, 1);
            if (s < MAXNBR) { snb[s] = j; sdx[s] = dx; sdy[s] = dy; }
        }
    }
    __syncthreads();
    int cnt = min(scnt, MAXNBR);
    float wx = c2W[64 * 128 + tid];
    float wy = c2W[65 * 128 + tid];
    float mx = -1e9f;
    const float* pb = g_p2 + (size_t)b * N * F;
    int n = 0;
    for (; n + 4 <= cnt; n += 4) {
        float v0 = pb[snb[n] * F + tid];
        float v1 = pb[snb[n + 1] * F + tid];
        float v2 = pb[snb[n + 2] * F + tid];
        float v3 = pb[snb[n + 3] * F + tid];
        float m0 = fmaf(sdx[n], wx, fmaf(sdy[n], wy, v0));
        float m1 = fmaf(sdx[n + 1], wx, fmaf(sdy[n + 1], wy, v1));
        float m2 = fmaf(sdx[n + 2], wx, fmaf(sdy[n + 2], wy, v2));
        float m3 = fmaf(sdx[n + 3], wx, fmaf(sdy[n + 3], wy, v3));
        mx = fmaxf(mx, fmaxf(fmaxf(m0, m1), fmaxf(m2, m3)));
    }
    for (; n < cnt; n++) {
        float m = fmaf(sdx[n], wx, fmaf(sdy[n], wy, pb[snb[n] * F + tid]));
        mx = fmaxf(mx, m);
    }
    g_h2[((size_t)b * M + i) * F + tid] = mx;
}

// ---------------- final projection + partial max pool ---------------------
__global__ void final_partial(const float* __restrict__ W, const float* __restrict__ bias) {
    int fchunk = blockIdx.x, rchunk = blockIdx.y, b = blockIdx.z;
    int tid = threadIdx.x;  // 128
    int f = fchunk * 128 + tid;
    __shared__ float sh[64][132];
    int r0 = rchunk * 64;
    for (int e = tid; e < 64 * 130; e += 128) {
        int r = e / 130, c = e % 130;
        float v;
        if (c < 128) v = g_h2[((size_t)b * M2_ + r0 + r) * 128 + c];
        else         v = g_ctr2[(b * M2_ + r0 + r) * 2 + (c - 128)];
        sh[r][c] = v;
    }
    __syncthreads();
    float acc[64];
#pragma unroll
    for (int r = 0; r < 64; r++) acc[r] = 0.0f;
    for (int c = 0; c < 130; c++) {
        float w = W[c * 1024 + f];
#pragma unroll
        for (int r = 0; r < 64; r++) acc[r] = fmaf(sh[r][c], w, acc[r]);
    }
    float mx = acc[0];
#pragma unroll
    for (int r = 1; r < 64; r++) mx = fmaxf(mx, acc[r]);
    g_pmax[(b * 8 + rchunk) * 1024 + f] = mx + bias[f];
}

__global__ void final_reduce(float* __restrict__ gf) {
    int b = blockIdx.x, f = threadIdx.x;  // 1024
    float mx = g_pmax[(b * 8) * 1024 + f];
#pragma unroll
    for (int r = 1; r < 8; r++) mx = fmaxf(mx, g_pmax[(b * 8 + r) * 1024 + f]);
    gf[b * 1024 + f] = mx;
}

// ---------------- launch ---------------------------------------------------
extern "C" void kernel_launch(void* const* d_in, const int* in_sizes, int n_in,
                              void* d_out, int out_size) {
    const float* x     = (const float*)d_in[0];
    const float* zones = (const float*)d_in[1];
    const float* lf_W1 = (const float*)d_in[2];
    const float* lf_b1 = (const float*)d_in[3];
    const float* lf_W2 = (const float*)d_in[4];
    const float* lf_b2 = (const float*)d_in[5];
    const float* c1_W  = (const float*)d_in[6];
    const float* c1_b  = (const float*)d_in[7];
    const float* c2_W  = (const float*)d_in[8];
    const float* c2_b  = (const float*)d_in[9];
    const float* c3_W  = (const float*)d_in[10];
    const float* c3_b  = (const float*)d_in[11];

    float* lf_out = (float*)d_out;
    float* gf_out = (float*)d_out + (size_t)B_ * N_ * LF_;

    lf_kernel<<<(B_ * N_) / 32, 64>>>(x, lf_W1, lf_b1, lf_W2, lf_b2, lf_out);
    p1_kernel<<<(B_ * N_) / 32, 64>>>(lf_out, zones, c1_W, c1_b);
    fps_kernel<8, N_, M1_, 0><<<B_, 512>>>(x);
    sa1_kernel<<<dim3(M1_, B_), 128>>>(x, c1_W);
    fps_kernel<4, M1_, M2_, 1><<<B_, 512>>>(nullptr);
    p2_kernel<<<(B_ * M1_) / 32, 128>>>(c2_W, c2_b);
    sa2_kernel<<<dim3(M2_, B_), F2_>>>(c2_W);
    final_partial<<<dim3(8, 8, B_), 128>>>(c3_W, c3_b);
    final_reduce<<<B_, 1024>>>(gf_out);
}